// round 17
// baseline (speedup 1.0000x reference)
#include <cuda_runtime.h>
#include <cuda_fp16.h>
#include <cstdint>

// Conv2D 3x3 SAME stride-1, mma.sync.m16n8k16.f16 (fp32 accum).
// Round-17: split A-staging. Taps 0-2 only read planes {0,1}; plane 2 is first
// read at tap 3, plane 3 at tap 6. Stage planes 0-1 in the prologue, defer
// planes 2/3 into the t=0/t=1 tap bodies where their LDG latency hides under
// MMAs (published by the existing per-tap __syncthreads before first use).
// Otherwise identical to round 16: weights on m16 A-side / pixels on n8 B-side
// (both non-trans LDSM), CTA M=128 x N=128, 128 thr, 4 warps 64x64, 2 CTAs/SM.

#define CH 128
#define CW 128
#define CIN 64
#define COUT 128
#define NTAP 9
#define NB 16

#define W_WORDS (NTAP*COUT*32)
__device__ __align__(16) uint32_t g_wh[W_WORDS];

#define APW 36                       // A pixel-row stride in words (144 B)
#define A_PLANE_W (66*APW)           // 66 pixel rows (64 strip + 2 halo)
#define AS_WORDS (4*A_PLANE_W)       // 9504 words
#define B_BYTES 16384                // one tap weight image
#define SMEM_BYTES (AS_WORDS*4 + 2*B_BYTES)   // 70,784 B -> 2 CTAs/SM

#define MMA_F16(c, a, b0, b1) \
    asm volatile("mma.sync.aligned.m16n8k16.row.col.f32.f16.f16.f32 " \
        "{%0,%1,%2,%3}, {%4,%5,%6,%7}, {%8,%9}, {%0,%1,%2,%3};" \
        : "+f"((c)[0]), "+f"((c)[1]), "+f"((c)[2]), "+f"((c)[3]) \
        : "r"((a)[0]), "r"((a)[1]), "r"((a)[2]), "r"((a)[3]), \
          "r"(b0), "r"(b1))

#define LDSM4(r0, r1, r2, r3, addr) \
    asm volatile("ldmatrix.sync.aligned.m8n8.x4.shared.b16 {%0,%1,%2,%3}, [%4];" \
        : "=r"(r0), "=r"(r1), "=r"(r2), "=r"(r3) : "r"(addr))

static __device__ __forceinline__ uint32_t smem_u32(const void* p) {
    uint32_t a;
    asm("{ .reg .u64 t; cvta.to.shared.u64 t, %1; cvt.u32.u64 %0, t; }" : "=r"(a) : "l"(p));
    return a;
}
static __device__ __forceinline__ void cp16(uint32_t dst, const void* src) {
    asm volatile("cp.async.ca.shared.global [%0], [%1], 16;"
                 :: "r"(dst), "l"(src) : "memory");
}
static __device__ __forceinline__ uint32_t pack2(float lo, float hi) {
    __half2 h = __floats2half2_rn(lo, hi);
    return *(uint32_t*)&h;
}

// ---- pre-kernel: w [tap][k][co] -> fp16 [tap][co][k], XOR-swizzled 16B chunks ----
__global__ void cvt_w_kernel(const float* __restrict__ wt) {
    const int tid = blockIdx.x * blockDim.x + threadIdx.x;
    if (tid >= NTAP * CIN * COUT) return;
    const int co = tid & 127;
    const int k  = (tid >> 7) & 63;
    const int t  = tid >> 13;
    __half* dst = (__half*)g_wh;
    const int half_idx = (t * COUT + co) * 64 + (((k >> 3) ^ (co & 7)) << 3) + (k & 7);
    dst[half_idx] = __float2half(wt[tid]);
}

// stage A chunks [c_lo, c_hi): chunk = plane*528 + prow*8 + c8 (16B fp16 each)
static __device__ __forceinline__ void stage_A_range(
    uint32_t* smem, const float* __restrict__ xb,
    int h0, int ps, int tid, int c_lo, int c_hi) {
    for (int c = c_lo + tid; c < c_hi; c += 128) {
        const int plane = c / 528;
        const int rem   = c - plane * 528;
        const int prow  = rem >> 3;
        const int c8    = rem & 7;
        const int hr = h0 - 1 + plane;
        const int gp = ps - 1 + prow;
        uint4 tv = make_uint4(0u, 0u, 0u, 0u);
        if (((unsigned)hr < (unsigned)CH) && ((unsigned)gp < (unsigned)CW)) {
            const float4* s = (const float4*)(xb + (((size_t)hr * CW + gp) << 6) + (c8 << 3));
            const float4 a0 = s[0];
            const float4 a1 = s[1];
            tv.x = pack2(a0.x, a0.y); tv.y = pack2(a0.z, a0.w);
            tv.z = pack2(a1.x, a1.y); tv.w = pack2(a1.z, a1.w);
        }
        *(uint4*)((char*)smem + (plane * A_PLANE_W + prow * APW) * 4 + c8 * 16) = tv;
    }
}

// ---- main kernel ----
__global__ __launch_bounds__(128, 2)
void conv3x3_split_kernel(const float* __restrict__ x,
                          const float* __restrict__ bias,
                          float* __restrict__ out) {
    extern __shared__ uint32_t smem[];
    const uint32_t sb  = smem_u32(smem);
    const uint32_t sbB = sb + AS_WORDS * 4;

    const int tid  = threadIdx.x;
    const int wid  = tid >> 5;
    const int lane = tid & 31;
    const int gid  = lane >> 2;
    const int t4   = lane & 3;
    const int warp_m = wid >> 1;         // 0..1 : output row
    const int warp_n = wid & 1;          // 0..1 : cout half

    const int bx = blockIdx.x;
    const int n  = bx >> 7;
    const int r  = bx & 127;
    const int h0 = (r >> 1) << 1;        // output rows h0, h0+1
    const int ps = (r & 1) << 6;         // pixel strip base: 0 or 64

    // ---- B tap 0 via cp.async first (overlaps A staging) ----
#pragma unroll
    for (int i = 0; i < 8; ++i) {
        const int c = tid + i * 128;
        cp16(sbB + c * 16, g_wh + c * 4);
    }
    asm volatile("cp.async.commit_group;");

    // ---- stage A planes 0,1 only (taps 0-2 read only these) ----
    const float* xb = x + (size_t)n * CH * CW * CIN;
    stage_A_range(smem, xb, h0, ps, tid, 0, 1056);

    // ---- accumulators: [ci 4 co-groups][ni 8 px-groups], row=cout col=pixel ----
    float acc[4][8][4];
#pragma unroll
    for (int ci = 0; ci < 4; ++ci)
#pragma unroll
        for (int ni = 0; ni < 8; ++ni)
#pragma unroll
            for (int q = 0; q < 4; ++q) acc[ci][ni][q] = 0.0f;

    const int xlane = lane & 7;
    const uint32_t wrow = (uint32_t)((warp_n * 64 + (lane & 15)) * 128);
    const int whalf = lane >> 4;
    const uint32_t laddrP = (uint32_t)((((lane & 7) + ((lane >> 4) << 3)) * 144)
                                       + (((lane >> 3) & 1) << 4));

    // ---- mainloop: 9 taps, B double-buffered; planes 2/3 staged in t=0/1 ----
#pragma unroll 1
    for (int t = 0; t < 9; ++t) {
        asm volatile("cp.async.wait_group 0;" ::: "memory");
        __syncthreads();    // B[t] + staged A planes visible; B buf[(t+1)&1] free

        if (t < 8) {        // stage next tap, overlapped with this tap's MMAs
            const uint32_t dst = sbB + (uint32_t)(((t + 1) & 1) * B_BYTES);
            const uint32_t* src = g_wh + (t + 1) * 4096;
#pragma unroll
            for (int i = 0; i < 8; ++i) {
                const int c = tid + i * 128;
                cp16(dst + c * 16, src + c * 4);
            }
            asm volatile("cp.async.commit_group;");
        }
        // deferred A staging: plane 2 during tap 0 (first read tap 3),
        // plane 3 during tap 1 (first read tap 6). Published by the
        // __syncthreads at the top of taps 3 / 6 respectively.
        if (t == 0)      stage_A_range(smem, xb, h0, ps, tid, 1056, 1584);
        else if (t == 1) stage_A_range(smem, xb, h0, ps, tid, 1584, 2112);

        const int kh = (t * 11) >> 5;            // t/3
        const int kw = t - kh * 3;
        const uint32_t pbase = sb + (uint32_t)((warp_m + kh) * (A_PLANE_W * 4)
                                   + kw * 144) + laddrP;
        const uint32_t wbase = sbB + (uint32_t)((t & 1) * B_BYTES) + wrow;

#pragma unroll
        for (int ks = 0; ks < 4; ++ks) {
            uint32_t aw[4][4];
            const uint32_t wsw = (uint32_t)((((ks * 2 + whalf) ^ xlane)) << 4);
#pragma unroll
            for (int ci = 0; ci < 4; ++ci)
                LDSM4(aw[ci][0], aw[ci][1], aw[ci][2], aw[ci][3],
                      wbase + (uint32_t)(ci * 2048) + wsw);
            uint32_t bp[8][2];
#pragma unroll
            for (int j = 0; j < 4; ++j)
                LDSM4(bp[2 * j][0], bp[2 * j][1], bp[2 * j + 1][0], bp[2 * j + 1][1],
                      pbase + (uint32_t)(j * 2304 + ks * 32));
#pragma unroll
            for (int ci = 0; ci < 4; ++ci)
#pragma unroll
                for (int ni = 0; ni < 8; ++ni)
                    MMA_F16(acc[ci][ni], aw[ci], bp[ni][0], bp[ni][1]);
        }
    }

    // ---- epilogue: bias + store (row=cout, col=pixel frags) ----
    const int hrow = h0 + warp_m;
    float* orow = out + (((size_t)n * CH + hrow) * CW + ps) * COUT;

    float ba[4], bb[4];
#pragma unroll
    for (int ci = 0; ci < 4; ++ci) {
        const int co = warp_n * 64 + ci * 16 + gid;
        ba[ci] = bias[co];
        bb[ci] = bias[co + 8];
    }

#pragma unroll
    for (int ci = 0; ci < 4; ++ci) {
        const int co = warp_n * 64 + ci * 16 + gid;
#pragma unroll
        for (int ni = 0; ni < 8; ++ni) {
            const int px = ni * 8 + t4 * 2;
            float* p0 = orow + (size_t)px * COUT;
            p0[co]            = acc[ci][ni][0] + ba[ci];
            p0[COUT + co]     = acc[ci][ni][1] + ba[ci];
            p0[co + 8]        = acc[ci][ni][2] + bb[ci];
            p0[COUT + co + 8] = acc[ci][ni][3] + bb[ci];
        }
    }
}

extern "C" void kernel_launch(void* const* d_in, const int* in_sizes, int n_in,
                              void* d_out, int out_size) {
    const float* x    = (const float*)d_in[0];
    const float* wt   = (const float*)d_in[1];
    const float* bias = (const float*)d_in[2];
    float* out = (float*)d_out;

    cudaFuncSetAttribute(conv3x3_split_kernel,
                         cudaFuncAttributeMaxDynamicSharedMemorySize, SMEM_BYTES);

    cvt_w_kernel<<<(NTAP * CIN * COUT + 255) / 256, 256>>>(wt);

    dim3 grid(NB * CH);                          // 2048 CTAs
    conv3x3_split_kernel<<<grid, 128, SMEM_BYTES>>>(x, bias, out);
}